// round 13
// baseline (speedup 1.0000x reference)
#include <cuda_runtime.h>

#define BB   4
#define HH   256
#define WW   256
#define CC   32
#define KF   5
#define NTAP 25

#define TW   16                 // tile width (px)
#define TH   8                  // tile height (2 rows/warp, 4 warps, 128 thr)
#define NTHR 128
#define TSS  132                // u64 stride per tap row (16B aligned, padded)
#define SMEM_BYTES (NTAP * TSS * 8)   // 26400 B

typedef unsigned long long u64;

__device__ __forceinline__ void fma2(u64& d, u64 a, u64 b) {
    asm("fma.rn.f32x2 %0, %1, %2, %0;" : "+l"(d) : "l"(a), "l"(b));
}
__device__ __forceinline__ u64 splat2(float v) {
    unsigned int b = __float_as_uint(v);
    return ((u64)b << 32) | b;
}

// one (feat-window, out-row): 5 j-taps x 8 px x 2 ch (packed), FFMA2
// acc[8]: one u64 (2ch) per px. W[12]: 12 cols x 1 ch-pair. taps splatted u64.
__device__ __forceinline__ void accum(u64* __restrict__ acc,
                                      const u64* __restrict__ W,
                                      const u64* __restrict__ tsp)
{
    #pragma unroll
    for (int j = 0; j < KF; j++) {
        const u64* tp = tsp + j * TSS;
        const ulonglong2 t01 = *(const ulonglong2*)(tp + 0);   // taps px0,1
        const ulonglong2 t23 = *(const ulonglong2*)(tp + 2);   // taps px2,3
        const ulonglong2 t45 = *(const ulonglong2*)(tp + 4);   // taps px4,5
        const ulonglong2 t67 = *(const ulonglong2*)(tp + 6);   // taps px6,7
        fma2(acc[0], W[0 + j], t01.x);
        fma2(acc[1], W[1 + j], t01.y);
        fma2(acc[2], W[2 + j], t23.x);
        fma2(acc[3], W[3 + j], t23.y);
        fma2(acc[4], W[4 + j], t45.x);
        fma2(acc[5], W[5 + j], t45.y);
        fma2(acc[6], W[6 + j], t67.x);
        fma2(acc[7], W[7 + j], t67.y);
    }
}

__global__ void __launch_bounds__(NTHR, 6)
kpc2d_kernel(const float* __restrict__ feat,
             const float* __restrict__ kern,
             const float* __restrict__ bias,
             float* __restrict__ out)
{
    extern __shared__ u64 ts[];   // [NTAP][TSS] splatted taps (t,t)

    const int tid  = threadIdx.x;
    const int lane = tid & 31;
    const int wid  = tid >> 5;          // warp -> rows 2*wid, 2*wid+1 (0..3)
    const int cp   = lane & 15;         // channel pair: ch 2cp, 2cp+1
    const int half = lane >> 4;         // pixel half
    const int w0   = blockIdx.x * TW;
    const int h0   = blockIdx.y * TH;
    const int bz   = blockIdx.z;

    // ---- tap fill: streaming LDG.128 + magic divide + splat STS.64 ----
    const float4* kern4 = (const float4*)kern;
    const unsigned kbase = (unsigned)((bz * HH + h0) * WW + w0) * NTAP;
    #pragma unroll 1
    for (unsigned idx4 = tid; idx4 < TH * TW * NTAP / 4; idx4 += NTHR) {
        const unsigned row = idx4 / 100u;
        const unsigned k4  = (idx4 - row * 100u) * 4u;   // 0..396
        const unsigned fidx = kbase + row * (unsigned)(WW * NTAP) + k4;
        const float4 v = __ldcs(kern4 + (fidx >> 2));    // read-once
        unsigned col = (k4 * 1311u) >> 15;               // k4/25 for k4<400
        unsigned tap = k4 - col * 25u;
        const unsigned pb = row * TW;
        float vv[4] = {v.x, v.y, v.z, v.w};
        #pragma unroll
        for (int e = 0; e < 4; e++) {
            ts[tap * TSS + pb + col] = splat2(vv[e]);
            if (++tap == 25u) { tap = 0u; col++; }
        }
    }

    const u64 bv = *(const u64*)(bias + 2 * cp);
    __syncthreads();

    // ---- compute: thread = 2 rows x 8 px x 2 ch (packed), FFMA2 ----
    u64 a0[8], a1[8];
    #pragma unroll
    for (int p = 0; p < 8; p++) { a0[p] = bv; a1[p] = bv; }

    const int r0    = wid * 2;
    const int pbase = half * 8;
    const u64* ts0  = ts + r0 * TW + pbase;    // row-0 tap pixel base
    const u64* ts1  = ts0 + TW;                // row-1 tap pixel base
    const bool interior = (h0 >= 2) && (h0 + TH + 2 <= HH) &&
                          (w0 >= 2) && (w0 + TW + 2 <= WW);

    const int fcol = ((bz * HH) * WW + (w0 + pbase - 2)) * CC + 2 * cp;

    if (interior) {
        #pragma unroll
        for (int g = 0; g < 6; g++) {
            const int gh = h0 + r0 + g - 2;
            const float* frow = feat + (fcol + gh * (WW * CC));
            u64 W[12];
            #pragma unroll
            for (int c = 0; c < 12; c++)
                W[c] = __ldg((const u64*)(frow + c * CC));
            if (g < 5) accum(a0, W, ts0 + (g    ) * (KF * TSS));
            if (g > 0) accum(a1, W, ts1 + (g - 1) * (KF * TSS));
        }
    } else {
        #pragma unroll 1
        for (int g = 0; g < 6; g++) {
            const int gh = h0 + r0 + g - 2;
            const bool rok = (unsigned)gh < HH;
            const float* frow = feat + (fcol + gh * (WW * CC));
            u64 W[12];
            #pragma unroll
            for (int c = 0; c < 12; c++) {
                const int gw = w0 + pbase + c - 2;
                W[c] = (rok && (unsigned)gw < WW)
                       ? __ldg((const u64*)(frow + c * CC)) : 0ULL;
            }
            if (g < 5) accum(a0, W, ts0 + (g    ) * (KF * TSS));
            if (g > 0) accum(a1, W, ts1 + (g - 1) * (KF * TSS));
        }
    }

    // ---- store: streaming, 2 rows x 8 px, STG.64 ----
    float* o0 = out + (((bz * HH + h0 + r0) * WW + (w0 + pbase)) * CC + 2 * cp);
    float* o1 = o0 + WW * CC;
    #pragma unroll
    for (int p = 0; p < 8; p++) {
        __stcs((long long*)(o0 + p * CC), (long long)a0[p]);
        __stcs((long long*)(o1 + p * CC), (long long)a1[p]);
    }
}

extern "C" void kernel_launch(void* const* d_in, const int* in_sizes, int n_in,
                              void* d_out, int out_size)
{
    const float* feat = (const float*)d_in[0];
    const float* kern = (const float*)d_in[1];
    const float* bias = (const float*)d_in[2];
    float* out = (float*)d_out;

    static bool attr_set = false;
    if (!attr_set) {
        cudaFuncSetAttribute(kpc2d_kernel,
                             cudaFuncAttributeMaxDynamicSharedMemorySize,
                             SMEM_BYTES);
        attr_set = true;
    }

    dim3 grid(WW / TW, HH / TH, BB);   // 16 x 32 x 4 = 2048 blocks
    kpc2d_kernel<<<grid, NTHR, SMEM_BYTES>>>(feat, kern, bias, out);
}

// round 14
// speedup vs baseline: 1.3840x; 1.3840x over previous
#include <cuda_runtime.h>

#define BB   4
#define HH   256
#define WW   256
#define CC   32
#define KF   5
#define NTAP 25

#define TW   16                 // tile width (px)
#define TH   8                  // tile height (2 rows/warp, 4 warps, 128 thr)
#define NTHR 128
#define TSS  132                // f32 stride per tap row (16B aligned, padded)
#define SMEM_BYTES (NTAP * TSS * 4)   // 13200 B

// single-row accum: 5 j-taps x 8 px x 2 ch, scalar FFMA
__device__ __forceinline__ void accum(float* __restrict__ acc,
                                      const float* __restrict__ W,
                                      const float* __restrict__ tsp)
{
    #pragma unroll
    for (int j = 0; j < KF; j++) {
        const float4 tA = *(const float4*)(tsp + j * TSS);
        const float4 tB = *(const float4*)(tsp + j * TSS + 4);
        acc[ 0] += W[2*(0+j)  ] * tA.x;  acc[ 1] += W[2*(0+j)+1] * tA.x;
        acc[ 2] += W[2*(1+j)  ] * tA.y;  acc[ 3] += W[2*(1+j)+1] * tA.y;
        acc[ 4] += W[2*(2+j)  ] * tA.z;  acc[ 5] += W[2*(2+j)+1] * tA.z;
        acc[ 6] += W[2*(3+j)  ] * tA.w;  acc[ 7] += W[2*(3+j)+1] * tA.w;
        acc[ 8] += W[2*(4+j)  ] * tB.x;  acc[ 9] += W[2*(4+j)+1] * tB.x;
        acc[10] += W[2*(5+j)  ] * tB.y;  acc[11] += W[2*(5+j)+1] * tB.y;
        acc[12] += W[2*(6+j)  ] * tB.z;  acc[13] += W[2*(6+j)+1] * tB.z;
        acc[14] += W[2*(7+j)  ] * tB.w;  acc[15] += W[2*(7+j)+1] * tB.w;
    }
}

// fused dual-row accum: both rows' taps loaded up-front per j, 32 FFMA
// interleaved -> 2 independent chains between LDS waits.
__device__ __forceinline__ void accum2(float* __restrict__ a0,
                                       float* __restrict__ a1,
                                       const float* __restrict__ W,
                                       const float* __restrict__ t0p,
                                       const float* __restrict__ t1p)
{
    #pragma unroll
    for (int j = 0; j < KF; j++) {
        const float4 tA0 = *(const float4*)(t0p + j * TSS);
        const float4 tB0 = *(const float4*)(t0p + j * TSS + 4);
        const float4 tA1 = *(const float4*)(t1p + j * TSS);
        const float4 tB1 = *(const float4*)(t1p + j * TSS + 4);
        a0[ 0] += W[2*(0+j)  ] * tA0.x;  a1[ 0] += W[2*(0+j)  ] * tA1.x;
        a0[ 1] += W[2*(0+j)+1] * tA0.x;  a1[ 1] += W[2*(0+j)+1] * tA1.x;
        a0[ 2] += W[2*(1+j)  ] * tA0.y;  a1[ 2] += W[2*(1+j)  ] * tA1.y;
        a0[ 3] += W[2*(1+j)+1] * tA0.y;  a1[ 3] += W[2*(1+j)+1] * tA1.y;
        a0[ 4] += W[2*(2+j)  ] * tA0.z;  a1[ 4] += W[2*(2+j)  ] * tA1.z;
        a0[ 5] += W[2*(2+j)+1] * tA0.z;  a1[ 5] += W[2*(2+j)+1] * tA1.z;
        a0[ 6] += W[2*(3+j)  ] * tA0.w;  a1[ 6] += W[2*(3+j)  ] * tA1.w;
        a0[ 7] += W[2*(3+j)+1] * tA0.w;  a1[ 7] += W[2*(3+j)+1] * tA1.w;
        a0[ 8] += W[2*(4+j)  ] * tB0.x;  a1[ 8] += W[2*(4+j)  ] * tB1.x;
        a0[ 9] += W[2*(4+j)+1] * tB0.x;  a1[ 9] += W[2*(4+j)+1] * tB1.x;
        a0[10] += W[2*(5+j)  ] * tB0.y;  a1[10] += W[2*(5+j)  ] * tB1.y;
        a0[11] += W[2*(5+j)+1] * tB0.y;  a1[11] += W[2*(5+j)+1] * tB1.y;
        a0[12] += W[2*(6+j)  ] * tB0.z;  a1[12] += W[2*(6+j)  ] * tB1.z;
        a0[13] += W[2*(6+j)+1] * tB0.z;  a1[13] += W[2*(6+j)+1] * tB1.z;
        a0[14] += W[2*(7+j)  ] * tB0.w;  a1[14] += W[2*(7+j)  ] * tB1.w;
        a0[15] += W[2*(7+j)+1] * tB0.w;  a1[15] += W[2*(7+j)+1] * tB1.w;
    }
}

__global__ void __launch_bounds__(NTHR, 7)
kpc2d_kernel(const float* __restrict__ feat,
             const float* __restrict__ kern,
             const float* __restrict__ bias,
             float* __restrict__ out)
{
    extern __shared__ float ts[];   // [NTAP][TSS] scalar taps

    const int tid  = threadIdx.x;
    const int lane = tid & 31;
    const int wid  = tid >> 5;          // warp -> rows 2*wid, 2*wid+1
    const int cp   = lane & 15;         // channel pair: ch 2cp, 2cp+1
    const int half = lane >> 4;         // pixel half
    const int w0   = blockIdx.x * TW;
    const int h0   = blockIdx.y * TH;
    const int bz   = blockIdx.z;

    // ---- tap fill: streaming LDG.128 + magic divide + transposed STS ----
    const float4* kern4 = (const float4*)kern;
    const unsigned kbase = (unsigned)((bz * HH + h0) * WW + w0) * NTAP;
    #pragma unroll 1
    for (unsigned idx4 = tid; idx4 < TH * TW * NTAP / 4; idx4 += NTHR) {
        const unsigned row = idx4 / 100u;
        const unsigned k4  = (idx4 - row * 100u) * 4u;   // 0..396
        const unsigned fidx = kbase + row * (unsigned)(WW * NTAP) + k4;
        const float4 v = __ldcs(kern4 + (fidx >> 2));
        unsigned col = (k4 * 1311u) >> 15;               // k4/25 for k4<400
        unsigned tap = k4 - col * 25u;
        const unsigned pb = row * TW;
        float vv[4] = {v.x, v.y, v.z, v.w};
        #pragma unroll
        for (int e = 0; e < 4; e++) {
            ts[tap * TSS + pb + col] = vv[e];
            if (++tap == 25u) { tap = 0u; col++; }
        }
    }

    const float2 bv = *(const float2*)(bias + 2 * cp);

    const int r0    = wid * 2;
    const int pbase = half * 8;
    const float* ts0 = ts + r0 * TW + pbase;
    const float* ts1 = ts0 + TW;
    const bool interior = (h0 >= 2) && (h0 + TH + 2 <= HH) &&
                          (w0 >= 2) && (w0 + TW + 2 <= WW);

    const int fcol = ((bz * HH) * WW + (w0 + pbase - 2)) * CC + 2 * cp;

    // ---- hoist g=0 feat loads above the barrier (independent of smem) ----
    float W[24];
    if (interior) {
        const float* frow = feat + (fcol + (h0 + r0 - 2) * (WW * CC));
        #pragma unroll
        for (int c = 0; c < 12; c++) {
            const float2 f = __ldg((const float2*)(frow + c * CC));
            W[2*c] = f.x; W[2*c+1] = f.y;
        }
    }

    __syncthreads();

    float a0[16], a1[16];
    #pragma unroll
    for (int p = 0; p < 8; p++) {
        a0[2*p] = bv.x; a0[2*p+1] = bv.y;
        a1[2*p] = bv.x; a1[2*p+1] = bv.y;
    }

    if (interior) {
        // g = 0: W already loaded, only row-0 consumes it
        accum(a0, W, ts0);
        #pragma unroll
        for (int g = 1; g < 6; g++) {
            const float* frow = feat + (fcol + (h0 + r0 + g - 2) * (WW * CC));
            #pragma unroll
            for (int c = 0; c < 12; c++) {
                const float2 f = __ldg((const float2*)(frow + c * CC));
                W[2*c] = f.x; W[2*c+1] = f.y;
            }
            if (g < 5) accum2(a0, a1, W, ts0 + g * (KF * TSS),
                                         ts1 + (g - 1) * (KF * TSS));
            else       accum(a1, W, ts1 + 4 * (KF * TSS));
        }
    } else {
        #pragma unroll 1
        for (int g = 0; g < 6; g++) {
            const int gh = h0 + r0 + g - 2;
            const bool rok = (unsigned)gh < HH;
            const float* frow = feat + (fcol + gh * (WW * CC));
            #pragma unroll
            for (int c = 0; c < 12; c++) {
                const int gw = w0 + pbase + c - 2;
                if (rok && (unsigned)gw < WW) {
                    const float2 f = __ldg((const float2*)(frow + c * CC));
                    W[2*c] = f.x; W[2*c+1] = f.y;
                } else {
                    W[2*c] = 0.f; W[2*c+1] = 0.f;
                }
            }
            if (g < 5) accum(a0, W, ts0 + (g    ) * (KF * TSS));
            if (g > 0) accum(a1, W, ts1 + (g - 1) * (KF * TSS));
        }
    }

    // ---- store: streaming, 2 rows x 8 px, STG.64 ----
    float* o0 = out + (((bz * HH + h0 + r0) * WW + (w0 + pbase)) * CC + 2 * cp);
    float* o1 = o0 + WW * CC;
    #pragma unroll
    for (int p = 0; p < 8; p++) {
        __stcs((float2*)(o0 + p * CC), make_float2(a0[2*p], a0[2*p+1]));
        __stcs((float2*)(o1 + p * CC), make_float2(a1[2*p], a1[2*p+1]));
    }
}

extern "C" void kernel_launch(void* const* d_in, const int* in_sizes, int n_in,
                              void* d_out, int out_size)
{
    const float* feat = (const float*)d_in[0];
    const float* kern = (const float*)d_in[1];
    const float* bias = (const float*)d_in[2];
    float* out = (float*)d_out;

    static bool attr_set = false;
    if (!attr_set) {
        cudaFuncSetAttribute(kpc2d_kernel,
                             cudaFuncAttributeMaxDynamicSharedMemorySize,
                             SMEM_BYTES);
        attr_set = true;
    }

    dim3 grid(WW / TW, HH / TH, BB);   // 16 x 32 x 4 = 2048 blocks
    kpc2d_kernel<<<grid, NTHR, SMEM_BYTES>>>(feat, kern, bias, out);
}